// round 16
// baseline (speedup 1.0000x reference)
#include <cuda_runtime.h>

// ---------------- problem constants ----------------
constexpr int   kNumNodes   = 120000;
constexpr int   kNumMovable = 100000;
constexpr int   kNumNets    = 100000;
constexpr int   kNumPins    = 400000;
constexpr int   kNbx = 256, kNby = 256;
constexpr int   kMap = kNbx * kNby;
constexpr float kBsx = 1000.0f / 256.0f;      // 3.90625 (exact in fp32)
constexpr float kBsy = 1000.0f / 256.0f;
constexpr float kInvBsx = 256.0f / 1000.0f;
constexpr float kInvBsy = 256.0f / 1000.0f;
constexpr float kEps = 1e-6f;
constexpr float kBinArea = kBsx * kBsy;
constexpr float kHNorm = 1.0f / (kBinArea * 1.5f);   // UNIT_H_CAP
constexpr float kVNorm = 1.0f / (kBinArea * 1.5f);   // UNIT_V_CAP

constexpr int kNetBlocks  = (kNumNets * 8 + 255) / 256;      // 3125
constexpr int kPrepBlocks = (kNumMovable + 255) / 256;       // 391

// ---------------- device scratch (no allocs allowed) ----------------
// g_scat4[m*kMap + x*256 + y] = {A', Bx', By', P}; one red.v4 per corner.
// Zero-initialized at load; scan_y re-zeros it in place each run.
__device__ float4 g_scat4[2 * kMap];
// g_T4[y*256+x] = {U1h, U2h, U1v, U2v}
__device__ float4 g_T4[kMap];
// per-cell {u, ry}; ry = exclusive x-prefix of util in the row; y-major
__device__ float2 g_uq[kMap];
// node prep scratch: A = {fxl, fxh, oy0, oy1}, B = {oy2, kxl, kxh, by0}
__device__ float4 g_prepA[kNumMovable];
__device__ float4 g_prepB[kNumMovable];

__device__ __forceinline__ void red4(float4* p, float a, float b, float c, float d) {
    asm volatile("red.global.add.v4.f32 [%0], {%1, %2, %3, %4};"
                 :: "l"(p), "f"(a), "f"(b), "f"(c), "f"(d) : "memory");
}

// Fused kernel: blocks [0, kNetBlocks) do the net bbox+scatter; blocks
// [kNetBlocks, kNetBlocks+kPrepBlocks) do node phase-1 (input loads + bin
// math -> packed scratch), which is independent of the util map and rides
// in the net phase's shadow (net is issue-bound, memory mostly idle).
__global__ void net_and_prep_kernel(const float* __restrict__ pin_pos,
                                    const int* __restrict__ netpin_start,
                                    const int* __restrict__ flat_netpin,
                                    const float* __restrict__ pos,
                                    const float* __restrict__ nsx,
                                    const float* __restrict__ nsy) {
    if (blockIdx.x >= kNetBlocks) {
        // ---- node phase-1: prep ----
        int m = (blockIdx.x - kNetBlocks) * blockDim.x + threadIdx.x;
        if (m >= kNumMovable) return;
        float xl = pos[m];
        float yl = pos[kNumNodes + m];
        float xh = xl + nsx[m];
        float yh = yl + nsy[m];
        int kxl = min(max(__float2int_rd(xl * kInvBsx), 0), kNbx - 1);
        int kxh = min(max(__float2int_rd(xh * kInvBsx), 0), kNbx - 1);
        float fxl = fminf(fmaxf(xl - (float)kxl * kBsx, 0.0f), kBsx);
        float fxh = fminf(fmaxf(xh - (float)kxh * kBsx, 0.0f), kBsx);
        int by0 = min(max(__float2int_rd(yl * kInvBsy), 0), kNby - 1);
        float oy0, oy1, oy2;
        {
            float ey = (float)by0 * kBsy;
            oy0 = fmaxf(fminf(yh, ey + kBsy) - fmaxf(yl, ey), 0.0f);
            ey += kBsy;
            oy1 = fmaxf(fminf(yh, ey + kBsy) - fmaxf(yl, ey), 0.0f);
            ey += kBsy;
            oy2 = fmaxf(fminf(yh, ey + kBsy) - fmaxf(yl, ey), 0.0f);
        }
        g_prepA[m] = make_float4(fxl, fxh, oy0, oy1);
        g_prepB[m] = make_float4(oy2, __int_as_float(kxl),
                                 __int_as_float(kxh), __int_as_float(by0));
        return;
    }

    // ---- net: 8 lanes per net, parallel pin reduction, per-lane scatter ----
    int t = blockIdx.x * blockDim.x + threadIdx.x;
    int n = t >> 3;               // net id
    int lane8 = threadIdx.x & 7;
    if (n >= kNumNets) return;    // aligned: whole 8-group exits together
    int s = netpin_start[n];
    int e = netpin_start[n + 1];

    float xmin = 1e30f, xmax = -1e30f, ymin = 1e30f, ymax = -1e30f;
    for (int p = s + lane8; p < e; p += 8) {
        int q    = __ldg(&flat_netpin[p]);
        float px = __ldg(&pin_pos[q]);
        float py = __ldg(&pin_pos[kNumPins + q]);
        xmin = fminf(xmin, px); xmax = fmaxf(xmax, px);
        ymin = fminf(ymin, py); ymax = fmaxf(ymax, py);
    }
#pragma unroll
    for (int o = 4; o >= 1; o >>= 1) {
        xmin = fminf(xmin, __shfl_xor_sync(0xffffffffu, xmin, o, 8));
        xmax = fmaxf(xmax, __shfl_xor_sync(0xffffffffu, xmax, o, 8));
        ymin = fminf(ymin, __shfl_xor_sync(0xffffffffu, ymin, o, 8));
        ymax = fmaxf(ymax, __shfl_xor_sync(0xffffffffu, ymax, o, 8));
    }
    if (e <= s) return;           // empty net -> no contribution

    float span_x = xmax - xmin;
    float span_y = ymax - ymin;
    float ch = (span_y > kEps) ? (1.0f / fmaxf(span_y, kEps)) : 0.0f;
    float cv = (span_x > kEps) ? (1.0f / fmaxf(span_x, kEps)) : 0.0f;

    // lane l -> (map = l>>2, i = (l>>1)&1, j = l&1)
    int mp = lane8 >> 2;
    int ii = (lane8 >> 1) & 1;
    int jj = lane8 & 1;
    float coef = mp ? cv : ch;
    if (coef == 0.0f) return;
    float va = ii ? xmax : xmin;
    float vb = jj ? ymax : ymin;
    int ka = min(max(__float2int_rd(va * kInvBsx), 0), kNbx - 1);
    int kb = min(max(__float2int_rd(vb * kInvBsy), 0), kNby - 1);
    float fa = fminf(fmaxf(va - (float)ka * kBsx, 0.0f), kBsx);
    float fb = fminf(fmaxf(vb - (float)kb * kBsy, 0.0f), kBsy);
    float w  = (ii == jj) ? coef : -coef;
    red4(&g_scat4[mp * kMap + ka * kNby + kb],
         w * (kBsx * kBsy), w * kBsx * fb, w * fa * kBsy, w * fa * fb);
}

// Quad inclusive suffix scan over a 256-thread block (4 independent values).
__device__ __forceinline__ void quad_block_suffix_scan(float& a, float& b,
                                                       float& c, float& d) {
    __shared__ float sm[4][8];
    int tid  = threadIdx.x;
    int lane = tid & 31;
    int w    = tid >> 5;
#pragma unroll
    for (int o = 1; o < 32; o <<= 1) {
        float ta = __shfl_down_sync(0xffffffffu, a, o);
        float tb = __shfl_down_sync(0xffffffffu, b, o);
        float tc = __shfl_down_sync(0xffffffffu, c, o);
        float td = __shfl_down_sync(0xffffffffu, d, o);
        if (lane + o < 32) { a += ta; b += tb; c += tc; d += td; }
    }
    if (lane == 0) { sm[0][w] = a; sm[1][w] = b; sm[2][w] = c; sm[3][w] = d; }
    __syncthreads();
    float xa = 0.f, xb = 0.f, xc = 0.f, xd = 0.f;
#pragma unroll
    for (int j = 0; j < 8; ++j) {
        if (j > w) { xa += sm[0][j]; xb += sm[1][j]; xc += sm[2][j]; xd += sm[3][j]; }
    }
    a += xa; b += xb; c += xc; d += xd;
}

// Dual inclusive suffix scan over a 256-thread block.
__device__ __forceinline__ void dual_block_suffix_scan(float v1, float v2,
                                                       float& o1, float& o2) {
    __shared__ float s1[8], s2[8];
    int tid  = threadIdx.x;
    int lane = tid & 31;
    int w    = tid >> 5;
    float x1 = v1, x2 = v2;
#pragma unroll
    for (int o = 1; o < 32; o <<= 1) {
        float t1 = __shfl_down_sync(0xffffffffu, x1, o);
        float t2 = __shfl_down_sync(0xffffffffu, x2, o);
        if (lane + o < 32) { x1 += t1; x2 += t2; }
    }
    if (lane == 0) { s1[w] = x1; s2[w] = x2; }   // warp suffix totals
    __syncthreads();
    float a1 = 0.f, a2 = 0.f;
#pragma unroll
    for (int j = 0; j < 8; ++j) {
        if (j > w) { a1 += s1[j]; a2 += s2[j]; }
    }
    o1 = x1 + a1;
    o2 = x2 + a2;
}

// Forward EXCLUSIVE prefix scan of one value over a 256-thread block.
__device__ __forceinline__ float block_prefix_excl(float v) {
    __shared__ float ws[8];
    int lane = threadIdx.x & 31;
    int w    = threadIdx.x >> 5;
    float x = v;
#pragma unroll
    for (int o = 1; o < 32; o <<= 1) {
        float t = __shfl_up_sync(0xffffffffu, x, o);
        if (lane >= o) x += t;
    }
    if (lane == 31) ws[w] = x;   // warp inclusive totals
    __syncthreads();
    float add = 0.f;
#pragma unroll
    for (int j = 0; j < 8; ++j) {
        if (j < w) add += ws[j];
    }
    return (x - v) + add;        // exclusive
}

// One block per x-row handling BOTH maps: quad suffix scan along y, then one
// packed STG.128 of {U1h,U2h,U1v,U2v} (transposed to y-major). Re-zeros scat.
__global__ void scan_y_kernel() {
    int x = blockIdx.x;           // 0..255
    int y = threadIdx.x;
    int ciH = x * kNby + y;
    int ciV = kMap + ciH;
    float4 cH = g_scat4[ciH];
    float4 cV = g_scat4[ciV];
    g_scat4[ciH] = make_float4(0.f, 0.f, 0.f, 0.f);
    g_scat4[ciV] = make_float4(0.f, 0.f, 0.f, 0.f);

    float sAh = cH.x, sByh = cH.z, sAv = cV.x, sByv = cV.z;
    quad_block_suffix_scan(sAh, sByh, sAv, sByv);    // inclusive

    float4 T;
    T.x = (sAh  - cH.x) + cH.y;   // U1h = SyExcl(A'h) + Bx'h
    T.y = (sByh - cH.z) + cH.w;   // U2h = SyExcl(By'h) + Ph
    T.z = (sAv  - cV.x) + cV.y;   // U1v
    T.w = (sByv - cV.z) + cV.w;   // U2v
    g_T4[y * kNbx + x] = T;       // transpose store, one STG.128
}

// Per y column: H = SxExcl(U1h) + U2h, V likewise; fused util map.
// One coalesced LDG.128; also stores {u, ry} per cell (x-prefix of util).
__global__ void scan_x_util_kernel() {
    int y = blockIdx.x;
    int x = threadIdx.x;
    int idx = y * kNbx + x;
    float4 tv = g_T4[idx];
    float sH, sV;
    dual_block_suffix_scan(tv.x, tv.z, sH, sV);      // inclusive
    float H = (sH - tv.x) + tv.y;                    // exclusive + U2
    float V = (sV - tv.z) + tv.w;
    float u = fmaxf(H * kHNorm, V * kVNorm);
    u = fminf(fmaxf(u, 0.5f), 2.0f);
    __syncthreads();                                 // smem reuse barrier
    float ry = block_prefix_excl(u);
    g_uq[idx] = make_float2(u, ry);
}

// Node phase-2 only: 2 coalesced LDG.128 of prep scratch, 6 util gathers,
// analytic x-integral per row, 1 store.
__global__ void node_kernel(float* __restrict__ out) {
    int m = blockIdx.x * blockDim.x + threadIdx.x;
    if (m >= kNumMovable) return;
    float4 a = g_prepA[m];
    float4 b = g_prepB[m];
    float fxl = a.x, fxh = a.y;
    float oy[3] = {a.z, a.w, b.x};
    int kxl = __float_as_int(b.y);
    int kxh = __float_as_int(b.z);
    int by0 = __float_as_int(b.w);

    float2 ql[3], qh[3];
#pragma unroll
    for (int j = 0; j < 3; ++j) {
        int yb = min(by0 + j, kNby - 1);
        const float2* qrow = g_uq + yb * kNbx;
        ql[j] = __ldg(&qrow[kxl]);
        qh[j] = __ldg(&qrow[kxh]);
    }

    float acc = 0.0f;
#pragma unroll
    for (int j = 0; j < 3; ++j) {
        float row = kBsx * (qh[j].y - ql[j].y) + fxh * qh[j].x - fxl * ql[j].x;
        acc += oy[j] * row;
    }
    out[m] = acc;
}

// ---------------- launcher ----------------
extern "C" void kernel_launch(void* const* d_in, const int* in_sizes, int n_in,
                              void* d_out, int out_size) {
    const float* pos          = (const float*)d_in[0];
    const float* pin_pos      = (const float*)d_in[1];
    const float* node_size_x  = (const float*)d_in[2];
    const float* node_size_y  = (const float*)d_in[3];
    const int*   netpin_start = (const int*)d_in[4];
    const int*   flat_netpin  = (const int*)d_in[5];
    float*       out          = (float*)d_out;

    net_and_prep_kernel<<<kNetBlocks + kPrepBlocks, 256>>>(
        pin_pos, netpin_start, flat_netpin, pos, node_size_x, node_size_y);
    scan_y_kernel<<<256, 256>>>();
    scan_x_util_kernel<<<256, 256>>>();
    node_kernel<<<(kNumMovable + 255) / 256, 256>>>(out);
}

// round 17
// speedup vs baseline: 1.0122x; 1.0122x over previous
#include <cuda_runtime.h>

// ---------------- problem constants ----------------
constexpr int   kNumNodes   = 120000;
constexpr int   kNumMovable = 100000;
constexpr int   kNumNets    = 100000;
constexpr int   kNumPins    = 400000;
constexpr int   kNbx = 256, kNby = 256;
constexpr int   kMap = kNbx * kNby;
constexpr float kBsx = 1000.0f / 256.0f;      // 3.90625 (exact in fp32)
constexpr float kBsy = 1000.0f / 256.0f;
constexpr float kInvBsx = 256.0f / 1000.0f;
constexpr float kInvBsy = 256.0f / 1000.0f;
constexpr float kEps = 1e-6f;
constexpr float kBinArea = kBsx * kBsy;
constexpr float kHNorm = 1.0f / (kBinArea * 1.5f);   // UNIT_H_CAP
constexpr float kVNorm = 1.0f / (kBinArea * 1.5f);   // UNIT_V_CAP

// ---------------- device scratch (no allocs allowed) ----------------
// g_scat4[m*kMap + x*256 + y] = {A', Bx', By', P}; one red.v4 per corner.
// Zero-initialized at load; scan_y re-zeros it in place each run.
__device__ float4 g_scat4[2 * kMap];
// g_T4[y*256+x] = {U1h, U2h, U1v, U2v}
__device__ float4 g_T4[kMap];
// per-cell {u, ry}; ry = exclusive x-prefix of util in the row; y-major
__device__ float2 g_uq[kMap];

__device__ __forceinline__ void red4(float4* p, float a, float b, float c, float d) {
    asm volatile("red.global.add.v4.f32 [%0], {%1, %2, %3, %4};"
                 :: "l"(p), "f"(a), "f"(b), "f"(c), "f"(d) : "memory");
}

// 8 lanes per net. Fast path: nets with <=8 pins (87%) use ONE predicated
// gather -> no loop, no branch divergence. Residual loop only for cnt>8
// (group-uniform branch). Then width-8 bbox reduction; each lane fires
// exactly one red.v4 for its (map, corner) slot.
__global__ void net_kernel(const float* __restrict__ pin_pos,
                           const int* __restrict__ netpin_start,
                           const int* __restrict__ flat_netpin) {
    int t = blockIdx.x * blockDim.x + threadIdx.x;
    int n = t >> 3;               // net id
    int lane8 = threadIdx.x & 7;
    if (n >= kNumNets) return;    // aligned: whole 8-group exits together
    int s = netpin_start[n];
    int e = netpin_start[n + 1];
    int cnt = e - s;

    float xmin = 1e30f, xmax = -1e30f, ymin = 1e30f, ymax = -1e30f;
    // branchless first round: predicated gather (no loop for cnt<=8)
    if (lane8 < cnt) {
        int q    = __ldg(&flat_netpin[s + lane8]);
        float px = __ldg(&pin_pos[q]);
        float py = __ldg(&pin_pos[kNumPins + q]);
        xmin = px; xmax = px; ymin = py; ymax = py;
    }
    // rare residual loop (group-uniform condition)
    if (cnt > 8) {
        for (int p = s + lane8 + 8; p < e; p += 8) {
            int q    = __ldg(&flat_netpin[p]);
            float px = __ldg(&pin_pos[q]);
            float py = __ldg(&pin_pos[kNumPins + q]);
            xmin = fminf(xmin, px); xmax = fmaxf(xmax, px);
            ymin = fminf(ymin, py); ymax = fmaxf(ymax, py);
        }
    }
    // width-8 subwarp reduction; all 8 lanes end with the full bbox
#pragma unroll
    for (int o = 4; o >= 1; o >>= 1) {
        xmin = fminf(xmin, __shfl_xor_sync(0xffffffffu, xmin, o, 8));
        xmax = fmaxf(xmax, __shfl_xor_sync(0xffffffffu, xmax, o, 8));
        ymin = fminf(ymin, __shfl_xor_sync(0xffffffffu, ymin, o, 8));
        ymax = fmaxf(ymax, __shfl_xor_sync(0xffffffffu, ymax, o, 8));
    }
    if (cnt <= 0) return;         // empty net -> no contribution

    float span_x = xmax - xmin;
    float span_y = ymax - ymin;
    float ch = (span_y > kEps) ? (1.0f / fmaxf(span_y, kEps)) : 0.0f;
    float cv = (span_x > kEps) ? (1.0f / fmaxf(span_x, kEps)) : 0.0f;

    // lane l -> (map = l>>2, i = (l>>1)&1, j = l&1)
    int mp = lane8 >> 2;
    int ii = (lane8 >> 1) & 1;
    int jj = lane8 & 1;
    float coef = mp ? cv : ch;
    if (coef == 0.0f) return;
    float va = ii ? xmax : xmin;
    float vb = jj ? ymax : ymin;
    int ka = min(max(__float2int_rd(va * kInvBsx), 0), kNbx - 1);
    int kb = min(max(__float2int_rd(vb * kInvBsy), 0), kNby - 1);
    float fa = fminf(fmaxf(va - (float)ka * kBsx, 0.0f), kBsx);
    float fb = fminf(fmaxf(vb - (float)kb * kBsy, 0.0f), kBsy);
    float w  = (ii == jj) ? coef : -coef;
    red4(&g_scat4[mp * kMap + ka * kNby + kb],
         w * (kBsx * kBsy), w * kBsx * fb, w * fa * kBsy, w * fa * fb);
}

// Quad inclusive suffix scan over a 256-thread block (4 independent values).
__device__ __forceinline__ void quad_block_suffix_scan(float& a, float& b,
                                                       float& c, float& d) {
    __shared__ float sm[4][8];
    int tid  = threadIdx.x;
    int lane = tid & 31;
    int w    = tid >> 5;
#pragma unroll
    for (int o = 1; o < 32; o <<= 1) {
        float ta = __shfl_down_sync(0xffffffffu, a, o);
        float tb = __shfl_down_sync(0xffffffffu, b, o);
        float tc = __shfl_down_sync(0xffffffffu, c, o);
        float td = __shfl_down_sync(0xffffffffu, d, o);
        if (lane + o < 32) { a += ta; b += tb; c += tc; d += td; }
    }
    if (lane == 0) { sm[0][w] = a; sm[1][w] = b; sm[2][w] = c; sm[3][w] = d; }
    __syncthreads();
    float xa = 0.f, xb = 0.f, xc = 0.f, xd = 0.f;
#pragma unroll
    for (int j = 0; j < 8; ++j) {
        if (j > w) { xa += sm[0][j]; xb += sm[1][j]; xc += sm[2][j]; xd += sm[3][j]; }
    }
    a += xa; b += xb; c += xc; d += xd;
}

// Dual inclusive suffix scan over a 256-thread block.
__device__ __forceinline__ void dual_block_suffix_scan(float v1, float v2,
                                                       float& o1, float& o2) {
    __shared__ float s1[8], s2[8];
    int tid  = threadIdx.x;
    int lane = tid & 31;
    int w    = tid >> 5;
    float x1 = v1, x2 = v2;
#pragma unroll
    for (int o = 1; o < 32; o <<= 1) {
        float t1 = __shfl_down_sync(0xffffffffu, x1, o);
        float t2 = __shfl_down_sync(0xffffffffu, x2, o);
        if (lane + o < 32) { x1 += t1; x2 += t2; }
    }
    if (lane == 0) { s1[w] = x1; s2[w] = x2; }   // warp suffix totals
    __syncthreads();
    float a1 = 0.f, a2 = 0.f;
#pragma unroll
    for (int j = 0; j < 8; ++j) {
        if (j > w) { a1 += s1[j]; a2 += s2[j]; }
    }
    o1 = x1 + a1;
    o2 = x2 + a2;
}

// Forward EXCLUSIVE prefix scan of one value over a 256-thread block.
__device__ __forceinline__ float block_prefix_excl(float v) {
    __shared__ float ws[8];
    int lane = threadIdx.x & 31;
    int w    = threadIdx.x >> 5;
    float x = v;
#pragma unroll
    for (int o = 1; o < 32; o <<= 1) {
        float t = __shfl_up_sync(0xffffffffu, x, o);
        if (lane >= o) x += t;
    }
    if (lane == 31) ws[w] = x;   // warp inclusive totals
    __syncthreads();
    float add = 0.f;
#pragma unroll
    for (int j = 0; j < 8; ++j) {
        if (j < w) add += ws[j];
    }
    return (x - v) + add;        // exclusive
}

// One block per x-row handling BOTH maps: quad suffix scan along y, then one
// packed STG.128 of {U1h,U2h,U1v,U2v} (transposed to y-major). Re-zeros scat.
__global__ void scan_y_kernel() {
    int x = blockIdx.x;           // 0..255
    int y = threadIdx.x;
    int ciH = x * kNby + y;
    int ciV = kMap + ciH;
    float4 cH = g_scat4[ciH];
    float4 cV = g_scat4[ciV];
    g_scat4[ciH] = make_float4(0.f, 0.f, 0.f, 0.f);
    g_scat4[ciV] = make_float4(0.f, 0.f, 0.f, 0.f);

    float sAh = cH.x, sByh = cH.z, sAv = cV.x, sByv = cV.z;
    quad_block_suffix_scan(sAh, sByh, sAv, sByv);    // inclusive

    float4 T;
    T.x = (sAh  - cH.x) + cH.y;   // U1h = SyExcl(A'h) + Bx'h
    T.y = (sByh - cH.z) + cH.w;   // U2h = SyExcl(By'h) + Ph
    T.z = (sAv  - cV.x) + cV.y;   // U1v
    T.w = (sByv - cV.z) + cV.w;   // U2v
    g_T4[y * kNbx + x] = T;       // transpose store, one STG.128
}

// Per y column: H = SxExcl(U1h) + U2h, V likewise; fused util map.
// One coalesced LDG.128; also stores {u, ry} per cell (x-prefix of util).
__global__ void scan_x_util_kernel() {
    int y = blockIdx.x;
    int x = threadIdx.x;
    int idx = y * kNbx + x;
    float4 tv = g_T4[idx];
    float sH, sV;
    dual_block_suffix_scan(tv.x, tv.z, sH, sV);      // inclusive
    float H = (sH - tv.x) + tv.y;                    // exclusive + U2
    float V = (sV - tv.z) + tv.w;
    float u = fmaxf(H * kHNorm, V * kVNorm);
    u = fminf(fmaxf(u, 0.5f), 2.0f);
    __syncthreads();                                 // smem reuse barrier
    float ry = block_prefix_excl(u);
    g_uq[idx] = make_float2(u, ry);
}

// One thread per node. X handled analytically per row via
//   rowint = bs*(ry[kxh]-ry[kxl]) + fxh*u[kxh] - fxl*u[kxl].
// Y explicit over <=3 rows (node_size_y < 4 < 2*bs). 512-thread blocks.
__global__ void node_kernel(const float* __restrict__ pos,
                            const float* __restrict__ nsx,
                            const float* __restrict__ nsy,
                            float* __restrict__ out) {
    int m = blockIdx.x * blockDim.x + threadIdx.x;
    if (m >= kNumMovable) return;
    float xl = pos[m];
    float yl = pos[kNumNodes + m];
    float xh = xl + nsx[m];
    float yh = yl + nsy[m];

    int kxl = min(max(__float2int_rd(xl * kInvBsx), 0), kNbx - 1);
    int kxh = min(max(__float2int_rd(xh * kInvBsx), 0), kNbx - 1);
    float fxl = fminf(fmaxf(xl - (float)kxl * kBsx, 0.0f), kBsx);
    float fxh = fminf(fmaxf(xh - (float)kxh * kBsx, 0.0f), kBsx);
    int by0 = min(max(__float2int_rd(yl * kInvBsy), 0), kNby - 1);

    float oy[3];
#pragma unroll
    for (int j = 0; j < 3; ++j) {
        float ey = (float)(by0 + j) * kBsy;
        oy[j] = fmaxf(fminf(yh, ey + kBsy) - fmaxf(yl, ey), 0.0f);
    }

    float2 ql[3], qh[3];
#pragma unroll
    for (int j = 0; j < 3; ++j) {
        int yb = min(by0 + j, kNby - 1);
        const float2* qrow = g_uq + yb * kNbx;
        ql[j] = __ldg(&qrow[kxl]);
        qh[j] = __ldg(&qrow[kxh]);
    }

    float acc = 0.0f;
#pragma unroll
    for (int j = 0; j < 3; ++j) {
        float row = kBsx * (qh[j].y - ql[j].y) + fxh * qh[j].x - fxl * ql[j].x;
        acc += oy[j] * row;
    }
    out[m] = acc;
}

// ---------------- launcher ----------------
extern "C" void kernel_launch(void* const* d_in, const int* in_sizes, int n_in,
                              void* d_out, int out_size) {
    const float* pos          = (const float*)d_in[0];
    const float* pin_pos      = (const float*)d_in[1];
    const float* node_size_x  = (const float*)d_in[2];
    const float* node_size_y  = (const float*)d_in[3];
    const int*   netpin_start = (const int*)d_in[4];
    const int*   flat_netpin  = (const int*)d_in[5];
    float*       out          = (float*)d_out;

    net_kernel<<<(kNumNets * 8 + 255) / 256, 256>>>(pin_pos, netpin_start, flat_netpin);
    scan_y_kernel<<<256, 256>>>();
    scan_x_util_kernel<<<256, 256>>>();
    node_kernel<<<(kNumMovable + 511) / 512, 512>>>(pos, node_size_x, node_size_y, out);
}